// round 16
// baseline (speedup 1.0000x reference)
#include <cuda_runtime.h>
#include <cuda_bf16.h>
#include <math.h>
#include <stdint.h>

// ---- problem constants ----
#define BB 4
#define NN 2048
#define DD 512
#define EE 8
#define HH 1365
#define TWOH 2730
#define CAP 320
#define BN (BB*NN)        // 8192
#define BE (BB*EE)        // 32
#define SLOTS (BE*CAP)    // 10240
#define ACTS 1376         // padded act row stride (43 chunks of 32)
#define W1HALF 1408       // padded width of u / g halves of converted w1
#define W1ROW  2816       // 2*W1HALF
#define W2KP   688        // padded k-pair rows of converted w2 (683 used)

// ---- scratch ----
__device__ __align__(16) uint32_t g_xgh[BN*DD/2];          // bf16x2 RMS-normed input
__device__ __align__(16) uint32_t g_acth[(SLOTS*ACTS)/2];  // bf16x2 GEGLU activations
__device__ __align__(16) uint32_t g_w1h[(size_t)EE*256*W1ROW]; // bf16x2 w1 [e][kp][u|g]
__device__ __align__(16) uint32_t g_w2h[(size_t)EE*W2KP*512];  // bf16x2 w2 [e][kp][n]
__device__ float g_eo[SLOTS*DD];
__device__ int   g_slot_tok[SLOTS];
__device__ int   g_e1[BN], g_e2[BN];
__device__ float g_g1[BN], g_g2[BN];
__device__ int   g_c1[BN], g_c2[BN];
__device__ unsigned char g_r2[BN];
__device__ int   g_total0[BE];
__device__ float g_dp[BE];
__device__ float g_zsum;

// ================= helpers =================
__device__ __forceinline__ uint32_t pack2(float lo, float hi){
    __nv_bfloat162 h = __floats2bfloat162_rn(lo, hi);
    return *reinterpret_cast<uint32_t*>(&h);
}
__device__ __forceinline__ void mma16(float* c,
        uint32_t a0, uint32_t a1, uint32_t a2, uint32_t a3,
        uint32_t b0, uint32_t b1){
    asm volatile(
        "mma.sync.aligned.m16n8k16.row.col.f32.bf16.bf16.f32 "
        "{%0,%1,%2,%3},{%4,%5,%6,%7},{%8,%9},{%0,%1,%2,%3};"
        : "+f"(c[0]), "+f"(c[1]), "+f"(c[2]), "+f"(c[3])
        : "r"(a0), "r"(a1), "r"(a2), "r"(a3), "r"(b0), "r"(b1));
}
__device__ __forceinline__ uint32_t s2u(const void* p){
    return (uint32_t)__cvta_generic_to_shared(p);
}
__device__ __forceinline__ void cp16(uint32_t saddr, const void* g){
    asm volatile("cp.async.cg.shared.global [%0], [%1], 16;" :: "r"(saddr), "l"(g));
}
#define CP_COMMIT() asm volatile("cp.async.commit_group;")
#define CP_WAIT2()  asm volatile("cp.async.wait_group 2;")
#define LDMX4(r0,r1,r2,r3,addr) \
    asm volatile("ldmatrix.sync.aligned.m8n8.x4.shared.b16 {%0,%1,%2,%3},[%4];" \
        : "=r"(r0),"=r"(r1),"=r"(r2),"=r"(r3) : "r"(addr))

// ================= threefry2x32 (JAX-compatible) =================
__device__ __forceinline__ uint32_t rotl32(uint32_t v, int r){ return (v<<r)|(v>>(32-r)); }
__device__ __forceinline__ void threefry2x32(uint32_t k0, uint32_t k1,
                                             uint32_t x0, uint32_t x1,
                                             uint32_t &o0, uint32_t &o1){
    uint32_t ks0 = k0, ks1 = k1, ks2 = 0x1BD11BDAu ^ k0 ^ k1;
    x0 += ks0; x1 += ks1;
#define TF_RND(r) { x0 += x1; x1 = rotl32(x1,(r)); x1 ^= x0; }
    TF_RND(13) TF_RND(15) TF_RND(26) TF_RND(6);  x0 += ks1; x1 += ks2 + 1u;
    TF_RND(17) TF_RND(29) TF_RND(16) TF_RND(24); x0 += ks2; x1 += ks0 + 2u;
    TF_RND(13) TF_RND(15) TF_RND(26) TF_RND(6);  x0 += ks0; x1 += ks1 + 3u;
    TF_RND(17) TF_RND(29) TF_RND(16) TF_RND(24); x0 += ks1; x1 += ks2 + 4u;
    TF_RND(13) TF_RND(15) TF_RND(26) TF_RND(6);  x0 += ks2; x1 += ks0 + 5u;
#undef TF_RND
    o0 = x0; o1 = x1;
}
__device__ __forceinline__ float bits_to_uniform(uint32_t b){
    return __uint_as_float((b >> 9) | 0x3f800000u) - 1.0f;
}

// ================= init (tiny: only gate accumulators) =================
__global__ void k_init(){
    int i = threadIdx.x;
    if (i < BE){ g_total0[i] = 0; g_dp[i] = 0.f; }
    if (i == 0) g_zsum = 0.f;
}

// ================= weight conversion (k-major, R9 layout) =================
// w1 [e][k=512][2730] -> g_w1h [e][kp=256][ u:1408 | g:1408 ] bf16x2(k,k+1)
__global__ void k_conv1(const float* __restrict__ w1){
    int idx = blockIdx.x * 256 + threadIdx.x;
    if (idx >= EE*256*2*(W1HALF/4)) return;
    int n4 = (idx % (W1HALF/4)) * 4;
    int r  = idx / (W1HALF/4);
    int h  = r & 1; r >>= 1;
    int kp = r & 255;
    int e  = r >> 8;
    const float* base = w1 + (size_t)e*DD*TWOH + (size_t)(2*kp)*TWOH + (h ? HH : 0);
    uint32_t o[4];
#pragma unroll
    for (int i = 0; i < 4; i++){
        int n = n4 + i;
        float lo = (n < HH) ? base[n]        : 0.f;
        float hi = (n < HH) ? base[TWOH + n] : 0.f;
        o[i] = pack2(lo, hi);
    }
    *reinterpret_cast<uint4*>(
        &g_w1h[((size_t)e*256 + kp)*W1ROW + h*W1HALF + n4]) = make_uint4(o[0],o[1],o[2],o[3]);
}

// w2 [e][k=1365][512] -> g_w2h [e][kp=688][512] bf16x2(k,k+1)
__global__ void k_conv2(const float* __restrict__ w2){
    int idx = blockIdx.x * 256 + threadIdx.x;
    if (idx >= EE*W2KP*128) return;
    int n4 = (idx & 127) * 4;
    int r  = idx >> 7;
    int kp = r % W2KP;
    int e  = r / W2KP;
    int k  = 2*kp;
    uint32_t o[4] = {0u,0u,0u,0u};
    if (k < HH){
        const float* r0 = w2 + ((size_t)e*HH + k)*DD + n4;
        float4 v0 = *reinterpret_cast<const float4*>(r0);
        float4 v1 = make_float4(0,0,0,0);
        if (k + 1 < HH) v1 = *reinterpret_cast<const float4*>(r0 + DD);
        o[0]=pack2(v0.x,v1.x); o[1]=pack2(v0.y,v1.y);
        o[2]=pack2(v0.z,v1.z); o[3]=pack2(v0.w,v1.w);
    }
    *reinterpret_cast<uint4*>(
        &g_w2h[((size_t)e*W2KP + kp)*512 + n4]) = make_uint4(o[0],o[1],o[2],o[3]);
}

// ================= K1: RMS norm + router (smem gw^T) =================
__global__ __launch_bounds__(256) void k_gate(const float* __restrict__ x,
                                              const float* __restrict__ gw,
                                              const float* __restrict__ png){
    __shared__ float sGT[8][516];
    __shared__ float sPn[512];
    __shared__ float s_p[8][8];
    __shared__ float s_z[8];
    int tid = threadIdx.x;
    int wib  = tid >> 5;
    int lane = tid & 31;
    int t    = blockIdx.x * 8 + wib;
    int bblk = (blockIdx.x * 8) / NN;

#pragma unroll
    for (int i = 0; i < 16; i++){
        int idx = i*256 + tid;
        sGT[idx & 7][idx >> 3] = gw[idx];
    }
    sPn[tid]       = png[tid];
    sPn[tid + 256] = png[tid + 256];
    __syncthreads();

    const float* xr = x + (size_t)t * DD;
    float4 v[4];
    float ss = 0.f;
#pragma unroll
    for (int j = 0; j < 4; j++){
        int d4 = (j*32 + lane) * 4;
        v[j] = *reinterpret_cast<const float4*>(xr + d4);
        ss += v[j].x*v[j].x + v[j].y*v[j].y + v[j].z*v[j].z + v[j].w*v[j].w;
    }
#pragma unroll
    for (int off = 16; off; off >>= 1) ss += __shfl_xor_sync(0xffffffffu, ss, off);
    float nrm = sqrtf(ss); nrm = fmaxf(nrm, 1e-12f);
    float scale = 22.62741699796952f / nrm;

    float xv[4][4];
#pragma unroll
    for (int j = 0; j < 4; j++){
        int d4 = (j*32 + lane) * 4;
        float4 pv = *reinterpret_cast<const float4*>(&sPn[d4]);
        xv[j][0] = v[j].x*scale*pv.x; xv[j][1] = v[j].y*scale*pv.y;
        xv[j][2] = v[j].z*scale*pv.z; xv[j][3] = v[j].w*scale*pv.w;
        uint2 pw = make_uint2(pack2(xv[j][0], xv[j][1]), pack2(xv[j][2], xv[j][3]));
        *reinterpret_cast<uint2*>(&g_xgh[((size_t)t*DD + d4) >> 1]) = pw;
    }

    float acc[8];
#pragma unroll
    for (int e = 0; e < 8; e++){
        float a = 0.f;
#pragma unroll
        for (int j = 0; j < 4; j++){
            int d4 = (j*32 + lane) * 4;
            float4 g4 = *reinterpret_cast<const float4*>(&sGT[e][d4]);
            a = fmaf(xv[j][0], g4.x, a); a = fmaf(xv[j][1], g4.y, a);
            a = fmaf(xv[j][2], g4.z, a); a = fmaf(xv[j][3], g4.w, a);
        }
        acc[e] = a;
    }
#pragma unroll
    for (int e = 0; e < 8; e++)
#pragma unroll
        for (int off = 16; off; off >>= 1)
            acc[e] += __shfl_xor_sync(0xffffffffu, acc[e], off);

    if (lane == 0){
        float m = acc[0];
#pragma unroll
        for (int e = 1; e < 8; e++) m = fmaxf(m, acc[e]);
        float p[8], s = 0.f;
#pragma unroll
        for (int e = 0; e < 8; e++){ p[e] = expf(acc[e]-m); s += p[e]; }
        float inv = 1.f / s;
        int e1 = 0; float v1 = p[0]*inv;
        int e2 = -1; float v2 = -1.f;
#pragma unroll
        for (int e = 1; e < 8; e++){
            float pe = p[e]*inv;
            if (pe > v1){ v2 = v1; e2 = e1; v1 = pe; e1 = e; }
            else if (pe > v2){ v2 = pe; e2 = e; }
        }
        float denom = fmaxf(v1+v2, 1e-9f);
        float gg1 = v1/denom, gg2 = v2/denom;
        uint32_t y0, y1;
        threefry2x32(0u, 42u, (uint32_t)t, (uint32_t)(t + 8192), y0, y1);
        float u1 = bits_to_uniform(y1);
        unsigned char r2 = (u1 < (gg2 / 0.2f)) ? 1 : 0;

        g_e1[t] = e1; g_e2[t] = e2;
        g_g1[t] = gg1; g_g2[t] = gg2; g_r2[t] = r2;
        g_c1[t] = -1; g_c2[t] = -1;                  // defaults (scan overwrites)
        atomicAdd(&g_total0[bblk*8 + e1], 1);
        float z = m + logf(s);
        s_z[wib] = z*z;
#pragma unroll
        for (int e = 0; e < 8; e++) s_p[wib][e] = p[e]*inv;
    }
    __syncthreads();
    if (tid < 8){
        float a = 0.f;
#pragma unroll
        for (int w = 0; w < 8; w++) a += s_p[w][tid];
        atomicAdd(&g_dp[bblk*8 + tid], a);
    } else if (tid == 8){
        float a = 0.f;
#pragma unroll
        for (int w = 0; w < 8; w++) a += s_z[w];
        atomicAdd(&g_zsum, a);
    }
}

// ================= K2: capacity scan + slot tail-fill + aux losses ==============
__global__ void k_scan(float* __restrict__ out, int out_size){
    int w = threadIdx.x >> 5;
    int lane = threadIdx.x & 31;
    int b = w >> 3, e = w & 7;
    int be = b*EE + e;
    int base1 = min(g_total0[be], CAP);
    int c0 = 0, c1 = 0;
    for (int n0 = 0; n0 < NN; n0 += 32){
        int n = n0 + lane;
        int t = b*NN + n;
        int m0 = (g_e1[t] == e);
        int m1 = (g_e2[t] == e) && g_r2[t];
        unsigned bal0 = __ballot_sync(0xffffffffu, m0);
        unsigned bal1 = __ballot_sync(0xffffffffu, m1);
        unsigned lt = (1u << lane) - 1u;
        if (m0){
            int pos = c0 + __popc(bal0 & lt);
            if (pos < CAP){ g_c1[t] = pos; g_slot_tok[be*CAP + pos] = n; }
        }
        if (m1){
            int pos = c1 + __popc(bal1 & lt) + base1;
            if (pos < CAP){ g_c2[t] = pos; g_slot_tok[be*CAP + pos] = n; }
        }
        c0 += __popc(bal0); c1 += __popc(bal1);
    }
    // fill unused slot tail with -1 (replaces bulk init)
    int fill = min(base1 + c1, CAP);
    for (int p = fill + lane; p < CAP; p += 32)
        g_slot_tok[be*CAP + p] = -1;

    // aux losses (inputs are all gate-produced; independent of scan body)
    if (threadIdx.x == 0 && out_size > BN*DD){
        float bal = 0.f;
        for (int q = 0; q < BE; q++){
            float dp = g_dp[q] * (1.f/(float)NN);
            float d1 = (float)min(g_total0[q], CAP) * (1.f/(float)NN);
            bal += dp * d1;
        }
        bal = bal * (1.f/(float)BE) * (float)(EE*EE);
        float zz = g_zsum * (1.f/(float)BN);
        out[BN*DD] = 0.01f * bal + 0.001f * zz;
    }
}

// ================= K3: GEMM1 (bf16 mma, 4-stage cp.async, 1 bar/chunk) ==========
// dyn smem: uA 4*1280 u32 | uBu 4*2176 | uBg 4*2176  = 90112 B
__global__ __launch_bounds__(256) void k_gemm1(const float* __restrict__ b1,
                                               const float* __restrict__ mb){
    extern __shared__ uint32_t dsm[];
    uint32_t* uA  = dsm;            // [s][m][20]
    uint32_t* uBu = dsm + 4*1280;   // [s][kp][136]
    uint32_t* uBg = uBu + 4*2176;
    __shared__ int sTok[64];

    int be = blockIdx.z, b = be >> 3, e = be & 7;
    int m0 = blockIdx.y * 64, n0 = blockIdx.x * 128;
    int tid = threadIdx.x;
    if (tid < 64) sTok[tid] = g_slot_tok[be*CAP + m0 + tid];
    __syncthreads();

    int lane = tid & 31, wid = tid >> 5;
    int group = lane >> 2, tig = lane & 3;
    int wm = wid >> 2, wn = wid & 3;

    int amr = tid & 63;
    int akb = (tid >> 6) * 8;          // k elem base 0/8/16/24
    int tokA = sTok[amr];
    const uint32_t* aSrc = (tokA >= 0)
        ? &g_xgh[((size_t)(b*NN + tokA)*DD + akb) >> 1] : nullptr;
    int bkp = tid >> 5;                // 0..7
    int bn4 = (tid & 31) * 4;
    const uint32_t* Wrow = g_w1h + (size_t)e*256*W1ROW;

    // zero A rows for empty slots in all 4 stages (stage skips them)
    if (tokA < 0){
#pragma unroll
        for (int s = 0; s < 4; s++)
            *reinterpret_cast<uint4*>(uA + s*1280 + amr*20 + (akb>>1)) = make_uint4(0,0,0,0);
    }

    float cu[2][4][4], cg[2][4][4];
#pragma unroll
    for (int i = 0; i < 2; i++)
#pragma unroll
        for (int j = 0; j < 4; j++)
#pragma unroll
            for (int r = 0; r < 4; r++){ cu[i][j][r] = 0.f; cg[i][j][r] = 0.f; }

#define G1_STAGE(s, cidx) {                                                     \
    if (aSrc) cp16(s2u(uA + (s)*1280 + amr*20 + (akb>>1)), aSrc + (cidx)*16);   \
    _Pragma("unroll")                                                           \
    for (int c2 = 0; c2 < 2; c2++){                                             \
        int kp_ = bkp + c2*8;                                                   \
        const uint32_t* wr_ = Wrow + (size_t)((cidx)*16 + kp_)*W1ROW + n0 + bn4;\
        cp16(s2u(uBu + (s)*2176 + kp_*136 + bn4), wr_);                         \
        cp16(s2u(uBg + (s)*2176 + kp_*136 + bn4), wr_ + W1HALF);                \
    } }

    const int NC = DD/32;   // 16
    G1_STAGE(0, 0); CP_COMMIT();
    G1_STAGE(1, 1); CP_COMMIT();
    G1_STAGE(2, 2); CP_COMMIT();
    for (int c = 0; c < NC; c++){
        CP_WAIT2();
        __syncthreads();
        int s = c & 3;
        uint32_t* pA  = uA  + s*1280;
        uint32_t* pBu = uBu + s*2176;
        uint32_t* pBg = uBg + s*2176;
#pragma unroll
        for (int ks = 0; ks < 2; ks++){
            int kpb = ks * 8;
            uint32_t a[2][4];
#pragma unroll
            for (int mi = 0; mi < 2; mi++){
                int row = wm*32 + mi*16 + (lane & 15);
                uint32_t addr = s2u(pA + row*20 + kpb + ((lane >> 4) << 2));
                LDMX4(a[mi][0], a[mi][1], a[mi][2], a[mi][3], addr);
            }
#pragma unroll
            for (int ni = 0; ni < 4; ni++){
                int nb = wn*32 + ni*8 + group;
                uint32_t bu0 = pBu[(kpb+tig)*136 + nb], bu1 = pBu[(kpb+tig+4)*136 + nb];
                uint32_t bg0 = pBg[(kpb+tig)*136 + nb], bg1 = pBg[(kpb+tig+4)*136 + nb];
#pragma unroll
                for (int mi = 0; mi < 2; mi++){
                    mma16(cu[mi][ni], a[mi][0],a[mi][1],a[mi][2],a[mi][3], bu0, bu1);
                    mma16(cg[mi][ni], a[mi][0],a[mi][1],a[mi][2],a[mi][3], bg0, bg1);
                }
            }
        }
        int nx = c + 3;
        if (nx < NC){ G1_STAGE(nx & 3, nx); }
        CP_COMMIT();
    }
#undef G1_STAGE

    // ---- GEGLU epilogue: packed bf16 pairs ----
    const float* b1e = b1 + (size_t)e * TWOH;
    const float* mbe = mb + (size_t)e * HH;
#pragma unroll
    for (int mi = 0; mi < 2; mi++){
#pragma unroll
        for (int rp = 0; rp < 2; rp++){
            int row = m0 + wm*32 + mi*16 + group + rp*8;
            size_t rowoff = ((size_t)be*CAP + row) * ACTS;
#pragma unroll
            for (int ni = 0; ni < 4; ni++){
                int col = n0 + wn*32 + ni*8 + tig*2;
                if (col < ACTS){
                    float lo = 0.f, hi = 0.f;
                    if (col < HH){
                        float u  = cu[mi][ni][rp*2]   + b1e[col];
                        float gv = cg[mi][ni][rp*2]   + b1e[col + HH];
                        lo = u * (0.5f * gv * (1.f + erff(gv * 0.7071067811865476f))) * mbe[col];
                    }
                    if (col + 1 < HH){
                        float u  = cu[mi][ni][rp*2+1] + b1e[col+1];
                        float gv = cg[mi][ni][rp*2+1] + b1e[col+1 + HH];
                        hi = u * (0.5f * gv * (1.f + erff(gv * 0.7071067811865476f))) * mbe[col+1];
                    }
                    g_acth[(rowoff + col) >> 1] = pack2(lo, hi);
                }
            }
        }
    }
}

// ================= K4: GEMM2 (bf16 mma, 4-stage cp.async, 1 bar/chunk) ==========
__global__ __launch_bounds__(256) void k_gemm2(const float* __restrict__ b2){
    __shared__ uint32_t sA[4][64][20];
    __shared__ uint32_t sB[4][16][136];

    int be = blockIdx.z, e = be & 7;
    int m0 = blockIdx.y * 64, n0 = blockIdx.x * 128;
    int tid = threadIdx.x;
    int lane = tid & 31, wid = tid >> 5;
    int group = lane >> 2, tig = lane & 3;
    int wm = wid >> 2, wn = wid & 3;

    int amr = tid & 63;
    int akb = (tid >> 6) * 8;
    const uint32_t* aSrc = &g_acth[(((size_t)be*CAP + m0 + amr)*ACTS + akb) >> 1];
    int bkp = tid >> 5;
    int bn4 = (tid & 31) * 4;
    const uint32_t* Wrow = g_w2h + (size_t)e*W2KP*512;

    float cc[2][4][4];
#pragma unroll
    for (int i = 0; i < 2; i++)
#pragma unroll
        for (int j = 0; j < 4; j++)
#pragma unroll
            for (int r = 0; r < 4; r++) cc[i][j][r] = 0.f;

#define G2_STAGE(s, cidx) {                                                     \
    cp16(s2u(&sA[s][amr][akb>>1]), aSrc + (cidx)*16);                           \
    _Pragma("unroll")                                                           \
    for (int c2 = 0; c2 < 2; c2++){                                             \
        int kp_ = bkp + c2*8;                                                   \
        cp16(s2u(&sB[s][kp_][bn4]), Wrow + (size_t)((cidx)*16 + kp_)*512 + n0 + bn4);\
    } }

    const int NC = ACTS/32;   // 43
    G2_STAGE(0, 0); CP_COMMIT();
    G2_STAGE(1, 1); CP_COMMIT();
    G2_STAGE(2, 2); CP_COMMIT();
    for (int c = 0; c < NC; c++){
        CP_WAIT2();
        __syncthreads();
        int s = c & 3;
#pragma unroll
        for (int ks = 0; ks < 2; ks++){
            int kpb = ks * 8;
            uint32_t a[2][4];
#pragma unroll
            for (int mi = 0; mi < 2; mi++){
                int row = wm*32 + mi*16 + (lane & 15);
                uint32_t addr = s2u(&sA[s][row][kpb + ((lane >> 4) << 2)]);
                LDMX4(a[mi][0], a[mi][1], a[mi][2], a[mi][3], addr);
            }
#pragma unroll
            for (int ni = 0; ni < 4; ni++){
                int nb = wn*32 + ni*8 + group;
                uint32_t b0 = sB[s][kpb+tig][nb], b1v = sB[s][kpb+tig+4][nb];
#pragma unroll
                for (int mi = 0; mi < 2; mi++)
                    mma16(cc[mi][ni], a[mi][0],a[mi][1],a[mi][2],a[mi][3], b0, b1v);
            }
        }
        int nx = c + 3;
        if (nx < NC){ G2_STAGE(nx & 3, nx); }
        CP_COMMIT();
    }
#undef G2_STAGE

    const float* b2e = b2 + (size_t)e * DD;
#pragma unroll
    for (int mi = 0; mi < 2; mi++){
#pragma unroll
        for (int rp = 0; rp < 2; rp++){
            int row = m0 + wm*32 + mi*16 + group + rp*8;
            float* orow = &g_eo[((size_t)be*CAP + row) * DD];
#pragma unroll
            for (int ni = 0; ni < 4; ni++){
                int col = n0 + wn*32 + ni*8 + tig*2;
                orow[col]   = cc[mi][ni][rp*2]   + b2e[col];
                orow[col+1] = cc[mi][ni][rp*2+1] + b2e[col+1];
            }
        }
    }
}

// ================= K5: combine + residual + LayerNorm =================
__global__ __launch_bounds__(256) void k_combine(const float* __restrict__ x,
                                                 const float* __restrict__ lng,
                                                 const float* __restrict__ lnb,
                                                 float* __restrict__ out){
    int t = blockIdx.x * 8 + (threadIdx.x >> 5);
    int lane = threadIdx.x & 31;
    int b = t / NN;
    int c1 = g_c1[t], c2 = g_c2[t];
    float w1g = (c1 >= 0) ? g_g1[t] : 0.f;
    float w2g = (c2 >= 0) ? g_g2[t] : 0.f;
    const float* eo1 = &g_eo[(((size_t)(b*EE + g_e1[t]))*CAP + (c1 >= 0 ? c1 : 0)) * DD];
    const float* eo2 = &g_eo[(((size_t)(b*EE + g_e2[t]))*CAP + (c2 >= 0 ? c2 : 0)) * DD];
    const float* xr = x + (size_t)t * DD;

    float y[16];
    float s = 0.f, s2 = 0.f;
#pragma unroll
    for (int j = 0; j < 4; j++){
        int d4 = (j*32 + lane) * 4;
        float4 xv = *reinterpret_cast<const float4*>(xr + d4);
        float4 a  = *reinterpret_cast<const float4*>(eo1 + d4);
        float4 c  = *reinterpret_cast<const float4*>(eo2 + d4);
        float yv[4] = { xv.x + w1g*a.x + w2g*c.x,
                        xv.y + w1g*a.y + w2g*c.y,
                        xv.z + w1g*a.z + w2g*c.z,
                        xv.w + w1g*a.w + w2g*c.w };
#pragma unroll
        for (int q = 0; q < 4; q++){
            y[j*4+q] = yv[q];
            s += yv[q]; s2 += yv[q]*yv[q];
        }
    }
#pragma unroll
    for (int off = 16; off; off >>= 1){
        s  += __shfl_xor_sync(0xffffffffu, s,  off);
        s2 += __shfl_xor_sync(0xffffffffu, s2, off);
    }
    float mu = s * (1.f/512.f);
    float var = s2 * (1.f/512.f) - mu*mu;
    float iv = rsqrtf(var + 1e-5f);
#pragma unroll
    for (int j = 0; j < 4; j++){
        int d4 = (j*32 + lane) * 4;
        float4 gv = *reinterpret_cast<const float4*>(lng + d4);
        float4 bv = *reinterpret_cast<const float4*>(lnb + d4);
        float4 ov;
        ov.x = (y[j*4+0]-mu)*iv*gv.x + bv.x;
        ov.y = (y[j*4+1]-mu)*iv*gv.y + bv.y;
        ov.z = (y[j*4+2]-mu)*iv*gv.z + bv.z;
        ov.w = (y[j*4+3]-mu)*iv*gv.w + bv.w;
        *reinterpret_cast<float4*>(out + (size_t)t*DD + d4) = ov;
    }
}

// ================= launch =================
extern "C" void kernel_launch(void* const* d_in, const int* in_sizes, int n_in,
                              void* d_out, int out_size){
    const float* x    = (const float*)d_in[0];
    const float* gw   = (const float*)d_in[1];
    const float* png  = (const float*)d_in[2];
    const float* w1   = (const float*)d_in[3];
    const float* b1   = (const float*)d_in[4];
    const float* mb   = (const float*)d_in[5];
    const float* w2   = (const float*)d_in[6];
    const float* b2   = (const float*)d_in[7];
    const float* lng  = (const float*)d_in[8];
    const float* lnb  = (const float*)d_in[9];
    float* out = (float*)d_out;

    const int G1_SMEM = (4*1280 + 4*2176 + 4*2176) * 4;   // 90112 B
    static bool attr_set = false;
    if (!attr_set){
        cudaFuncSetAttribute(k_gemm1, cudaFuncAttributeMaxDynamicSharedMemorySize, G1_SMEM);
        attr_set = true;
    }

    k_init<<<1, 64>>>();
    {
        int items1 = EE*256*2*(W1HALF/4);
        k_conv1<<<(items1 + 255)/256, 256>>>(w1);
        int items2 = EE*W2KP*128;
        k_conv2<<<(items2 + 255)/256, 256>>>(w2);
    }
    k_gate<<<BN/8, 256>>>(x, gw, png);
    k_scan<<<1, 1024>>>(out, out_size);
    k_gemm1<<<dim3((HH+127)/128, CAP/64, BE), 256, G1_SMEM>>>(b1, mb);
    k_gemm2<<<dim3(DD/128, CAP/64, BE), 256>>>(b2);
    k_combine<<<BN/8, 256>>>(x, lng, lnb, out);
}

// round 17
// speedup vs baseline: 1.4696x; 1.4696x over previous
#include <cuda_runtime.h>
#include <cuda_bf16.h>
#include <math.h>
#include <stdint.h>

// ---- problem constants ----
#define BB 4
#define NN 2048
#define DD 512
#define EE 8
#define HH 1365
#define TWOH 2730
#define CAP 320
#define BN (BB*NN)        // 8192
#define BE (BB*EE)        // 32
#define SLOTS (BE*CAP)    // 10240
#define ACTS 1376         // padded act row stride (43 chunks of 32)
#define W1HALF 1408       // padded width of u / g halves of converted w1
#define W1ROW  2816       // 2*W1HALF
#define W2KP   688        // padded k-pair rows of converted w2 (683 used)

// ---- scratch ----
__device__ __align__(16) uint32_t g_xgh[BN*DD/2];          // bf16x2 RMS-normed input
__device__ __align__(16) uint32_t g_acth[(SLOTS*ACTS)/2];  // bf16x2 GEGLU activations
__device__ __align__(16) uint32_t g_w1h[(size_t)EE*256*W1ROW]; // bf16x2 w1 [e][kp][u|g]
__device__ __align__(16) uint32_t g_w2h[(size_t)EE*W2KP*512];  // bf16x2 w2 [e][kp][n]
__device__ float g_eo[SLOTS*DD];
__device__ int   g_slot_tok[SLOTS];
__device__ int   g_e1[BN], g_e2[BN];
__device__ float g_g1[BN], g_g2[BN];
__device__ int   g_c1[BN], g_c2[BN];
__device__ unsigned char g_r2[BN];
__device__ int   g_total0[BE];
__device__ float g_dp[BE];
__device__ float g_zsum;

// ================= helpers =================
__device__ __forceinline__ uint32_t pack2(float lo, float hi){
    __nv_bfloat162 h = __floats2bfloat162_rn(lo, hi);
    return *reinterpret_cast<uint32_t*>(&h);
}
__device__ __forceinline__ void mma16(float* c,
        uint32_t a0, uint32_t a1, uint32_t a2, uint32_t a3,
        uint32_t b0, uint32_t b1){
    asm volatile(
        "mma.sync.aligned.m16n8k16.row.col.f32.bf16.bf16.f32 "
        "{%0,%1,%2,%3},{%4,%5,%6,%7},{%8,%9},{%0,%1,%2,%3};"
        : "+f"(c[0]), "+f"(c[1]), "+f"(c[2]), "+f"(c[3])
        : "r"(a0), "r"(a1), "r"(a2), "r"(a3), "r"(b0), "r"(b1));
}
__device__ __forceinline__ uint32_t s2u(const void* p){
    return (uint32_t)__cvta_generic_to_shared(p);
}
__device__ __forceinline__ void cp16(uint32_t saddr, const void* g){
    asm volatile("cp.async.cg.shared.global [%0], [%1], 16;" :: "r"(saddr), "l"(g));
}
#define CP_COMMIT() asm volatile("cp.async.commit_group;")
#define CP_WAIT1()  asm volatile("cp.async.wait_group 1;")
#define LDMX4(r0,r1,r2,r3,addr) \
    asm volatile("ldmatrix.sync.aligned.m8n8.x4.shared.b16 {%0,%1,%2,%3},[%4];" \
        : "=r"(r0),"=r"(r1),"=r"(r2),"=r"(r3) : "r"(addr))

// ================= threefry2x32 (JAX-compatible) =================
__device__ __forceinline__ uint32_t rotl32(uint32_t v, int r){ return (v<<r)|(v>>(32-r)); }
__device__ __forceinline__ void threefry2x32(uint32_t k0, uint32_t k1,
                                             uint32_t x0, uint32_t x1,
                                             uint32_t &o0, uint32_t &o1){
    uint32_t ks0 = k0, ks1 = k1, ks2 = 0x1BD11BDAu ^ k0 ^ k1;
    x0 += ks0; x1 += ks1;
#define TF_RND(r) { x0 += x1; x1 = rotl32(x1,(r)); x1 ^= x0; }
    TF_RND(13) TF_RND(15) TF_RND(26) TF_RND(6);  x0 += ks1; x1 += ks2 + 1u;
    TF_RND(17) TF_RND(29) TF_RND(16) TF_RND(24); x0 += ks2; x1 += ks0 + 2u;
    TF_RND(13) TF_RND(15) TF_RND(26) TF_RND(6);  x0 += ks0; x1 += ks1 + 3u;
    TF_RND(17) TF_RND(29) TF_RND(16) TF_RND(24); x0 += ks1; x1 += ks2 + 4u;
    TF_RND(13) TF_RND(15) TF_RND(26) TF_RND(6);  x0 += ks2; x1 += ks0 + 5u;
#undef TF_RND
    o0 = x0; o1 = x1;
}
__device__ __forceinline__ float bits_to_uniform(uint32_t b){
    return __uint_as_float((b >> 9) | 0x3f800000u) - 1.0f;
}

// ================= init (tiny: only gate accumulators) =================
__global__ void k_init(){
    int i = threadIdx.x;
    if (i < BE){ g_total0[i] = 0; g_dp[i] = 0.f; }
    if (i == 0) g_zsum = 0.f;
}

// ================= weight conversion (k-major, R9 layout) =================
// w1 [e][k=512][2730] -> g_w1h [e][kp=256][ u:1408 | g:1408 ] bf16x2(k,k+1)
__global__ void k_conv1(const float* __restrict__ w1){
    int idx = blockIdx.x * 256 + threadIdx.x;
    if (idx >= EE*256*2*(W1HALF/4)) return;
    int n4 = (idx % (W1HALF/4)) * 4;
    int r  = idx / (W1HALF/4);
    int h  = r & 1; r >>= 1;
    int kp = r & 255;
    int e  = r >> 8;
    const float* base = w1 + (size_t)e*DD*TWOH + (size_t)(2*kp)*TWOH + (h ? HH : 0);
    uint32_t o[4];
#pragma unroll
    for (int i = 0; i < 4; i++){
        int n = n4 + i;
        float lo = (n < HH) ? base[n]        : 0.f;
        float hi = (n < HH) ? base[TWOH + n] : 0.f;
        o[i] = pack2(lo, hi);
    }
    *reinterpret_cast<uint4*>(
        &g_w1h[((size_t)e*256 + kp)*W1ROW + h*W1HALF + n4]) = make_uint4(o[0],o[1],o[2],o[3]);
}

// w2 [e][k=1365][512] -> g_w2h [e][kp=688][512] bf16x2(k,k+1)
__global__ void k_conv2(const float* __restrict__ w2){
    int idx = blockIdx.x * 256 + threadIdx.x;
    if (idx >= EE*W2KP*128) return;
    int n4 = (idx & 127) * 4;
    int r  = idx >> 7;
    int kp = r % W2KP;
    int e  = r / W2KP;
    int k  = 2*kp;
    uint32_t o[4] = {0u,0u,0u,0u};
    if (k < HH){
        const float* r0 = w2 + ((size_t)e*HH + k)*DD + n4;
        float4 v0 = *reinterpret_cast<const float4*>(r0);
        float4 v1 = make_float4(0,0,0,0);
        if (k + 1 < HH) v1 = *reinterpret_cast<const float4*>(r0 + DD);
        o[0]=pack2(v0.x,v1.x); o[1]=pack2(v0.y,v1.y);
        o[2]=pack2(v0.z,v1.z); o[3]=pack2(v0.w,v1.w);
    }
    *reinterpret_cast<uint4*>(
        &g_w2h[((size_t)e*W2KP + kp)*512 + n4]) = make_uint4(o[0],o[1],o[2],o[3]);
}

// ================= K1: RMS norm + router (smem gw^T) =================
__global__ __launch_bounds__(256) void k_gate(const float* __restrict__ x,
                                              const float* __restrict__ gw,
                                              const float* __restrict__ png){
    __shared__ float sGT[8][516];
    __shared__ float sPn[512];
    __shared__ float s_p[8][8];
    __shared__ float s_z[8];
    int tid = threadIdx.x;
    int wib  = tid >> 5;
    int lane = tid & 31;
    int t    = blockIdx.x * 8 + wib;
    int bblk = (blockIdx.x * 8) / NN;

#pragma unroll
    for (int i = 0; i < 16; i++){
        int idx = i*256 + tid;
        sGT[idx & 7][idx >> 3] = gw[idx];
    }
    sPn[tid]       = png[tid];
    sPn[tid + 256] = png[tid + 256];
    __syncthreads();

    const float* xr = x + (size_t)t * DD;
    float4 v[4];
    float ss = 0.f;
#pragma unroll
    for (int j = 0; j < 4; j++){
        int d4 = (j*32 + lane) * 4;
        v[j] = *reinterpret_cast<const float4*>(xr + d4);
        ss += v[j].x*v[j].x + v[j].y*v[j].y + v[j].z*v[j].z + v[j].w*v[j].w;
    }
#pragma unroll
    for (int off = 16; off; off >>= 1) ss += __shfl_xor_sync(0xffffffffu, ss, off);
    float nrm = sqrtf(ss); nrm = fmaxf(nrm, 1e-12f);
    float scale = 22.62741699796952f / nrm;

    float xv[4][4];
#pragma unroll
    for (int j = 0; j < 4; j++){
        int d4 = (j*32 + lane) * 4;
        float4 pv = *reinterpret_cast<const float4*>(&sPn[d4]);
        xv[j][0] = v[j].x*scale*pv.x; xv[j][1] = v[j].y*scale*pv.y;
        xv[j][2] = v[j].z*scale*pv.z; xv[j][3] = v[j].w*scale*pv.w;
        uint2 pw = make_uint2(pack2(xv[j][0], xv[j][1]), pack2(xv[j][2], xv[j][3]));
        *reinterpret_cast<uint2*>(&g_xgh[((size_t)t*DD + d4) >> 1]) = pw;
    }

    float acc[8];
#pragma unroll
    for (int e = 0; e < 8; e++){
        float a = 0.f;
#pragma unroll
        for (int j = 0; j < 4; j++){
            int d4 = (j*32 + lane) * 4;
            float4 g4 = *reinterpret_cast<const float4*>(&sGT[e][d4]);
            a = fmaf(xv[j][0], g4.x, a); a = fmaf(xv[j][1], g4.y, a);
            a = fmaf(xv[j][2], g4.z, a); a = fmaf(xv[j][3], g4.w, a);
        }
        acc[e] = a;
    }
#pragma unroll
    for (int e = 0; e < 8; e++)
#pragma unroll
        for (int off = 16; off; off >>= 1)
            acc[e] += __shfl_xor_sync(0xffffffffu, acc[e], off);

    if (lane == 0){
        float m = acc[0];
#pragma unroll
        for (int e = 1; e < 8; e++) m = fmaxf(m, acc[e]);
        float p[8], s = 0.f;
#pragma unroll
        for (int e = 0; e < 8; e++){ p[e] = expf(acc[e]-m); s += p[e]; }
        float inv = 1.f / s;
        int e1 = 0; float v1 = p[0]*inv;
        int e2 = -1; float v2 = -1.f;
#pragma unroll
        for (int e = 1; e < 8; e++){
            float pe = p[e]*inv;
            if (pe > v1){ v2 = v1; e2 = e1; v1 = pe; e1 = e; }
            else if (pe > v2){ v2 = pe; e2 = e; }
        }
        float denom = fmaxf(v1+v2, 1e-9f);
        float gg1 = v1/denom, gg2 = v2/denom;
        uint32_t y0, y1;
        threefry2x32(0u, 42u, (uint32_t)t, (uint32_t)(t + 8192), y0, y1);
        float u1 = bits_to_uniform(y1);
        unsigned char r2 = (u1 < (gg2 / 0.2f)) ? 1 : 0;

        g_e1[t] = e1; g_e2[t] = e2;
        g_g1[t] = gg1; g_g2[t] = gg2; g_r2[t] = r2;
        g_c1[t] = -1; g_c2[t] = -1;                  // defaults (scan overwrites)
        atomicAdd(&g_total0[bblk*8 + e1], 1);
        float z = m + logf(s);
        s_z[wib] = z*z;
#pragma unroll
        for (int e = 0; e < 8; e++) s_p[wib][e] = p[e]*inv;
    }
    __syncthreads();
    if (tid < 8){
        float a = 0.f;
#pragma unroll
        for (int w = 0; w < 8; w++) a += s_p[w][tid];
        atomicAdd(&g_dp[bblk*8 + tid], a);
    } else if (tid == 8){
        float a = 0.f;
#pragma unroll
        for (int w = 0; w < 8; w++) a += s_z[w];
        atomicAdd(&g_zsum, a);
    }
}

// ================= K2: capacity scan + slot tail-fill + aux losses ==============
__global__ void k_scan(float* __restrict__ out, int out_size){
    int w = threadIdx.x >> 5;
    int lane = threadIdx.x & 31;
    int b = w >> 3, e = w & 7;
    int be = b*EE + e;
    int base1 = min(g_total0[be], CAP);
    int c0 = 0, c1 = 0;
    for (int n0 = 0; n0 < NN; n0 += 32){
        int n = n0 + lane;
        int t = b*NN + n;
        int m0 = (g_e1[t] == e);
        int m1 = (g_e2[t] == e) && g_r2[t];
        unsigned bal0 = __ballot_sync(0xffffffffu, m0);
        unsigned bal1 = __ballot_sync(0xffffffffu, m1);
        unsigned lt = (1u << lane) - 1u;
        if (m0){
            int pos = c0 + __popc(bal0 & lt);
            if (pos < CAP){ g_c1[t] = pos; g_slot_tok[be*CAP + pos] = n; }
        }
        if (m1){
            int pos = c1 + __popc(bal1 & lt) + base1;
            if (pos < CAP){ g_c2[t] = pos; g_slot_tok[be*CAP + pos] = n; }
        }
        c0 += __popc(bal0); c1 += __popc(bal1);
    }
    // fill unused slot tail with -1 (replaces bulk init)
    int fill = min(base1 + c1, CAP);
    for (int p = fill + lane; p < CAP; p += 32)
        g_slot_tok[be*CAP + p] = -1;

    // aux losses
    if (threadIdx.x == 0 && out_size > BN*DD){
        float bal = 0.f;
        for (int q = 0; q < BE; q++){
            float dp = g_dp[q] * (1.f/(float)NN);
            float d1 = (float)min(g_total0[q], CAP) * (1.f/(float)NN);
            bal += dp * d1;
        }
        bal = bal * (1.f/(float)BE) * (float)(EE*EE);
        float zz = g_zsum * (1.f/(float)BN);
        out[BN*DD] = 0.01f * bal + 0.001f * zz;
    }
}

// ================= K3: GEMM1 (bf16 mma, 3-stage cp.async, 1 bar/chunk) ==========
// dyn smem: uA 3*1280 u32 | uBu 3*2176 | uBg 3*2176  = 67584 B
__global__ __launch_bounds__(256) void k_gemm1(const float* __restrict__ b1,
                                               const float* __restrict__ mb){
    extern __shared__ uint32_t dsm[];
    uint32_t* uA  = dsm;            // [s][m][20]
    uint32_t* uBu = dsm + 3*1280;   // [s][kp][136]
    uint32_t* uBg = uBu + 3*2176;
    __shared__ int sTok[64];

    int be = blockIdx.z, b = be >> 3, e = be & 7;
    int m0 = blockIdx.y * 64, n0 = blockIdx.x * 128;
    int tid = threadIdx.x;
    if (tid < 64) sTok[tid] = g_slot_tok[be*CAP + m0 + tid];
    __syncthreads();

    int lane = tid & 31, wid = tid >> 5;
    int group = lane >> 2, tig = lane & 3;
    int wm = wid >> 2, wn = wid & 3;

    int amr = tid & 63;
    int akb = (tid >> 6) * 8;          // k elem base 0/8/16/24
    int tokA = sTok[amr];
    const uint32_t* aSrc = (tokA >= 0)
        ? &g_xgh[((size_t)(b*NN + tokA)*DD + akb) >> 1] : nullptr;
    int bkp = tid >> 5;                // 0..7
    int bn4 = (tid & 31) * 4;
    const uint32_t* Wrow = g_w1h + (size_t)e*256*W1ROW;

    if (tokA < 0){
#pragma unroll
        for (int s = 0; s < 3; s++)
            *reinterpret_cast<uint4*>(uA + s*1280 + amr*20 + (akb>>1)) = make_uint4(0,0,0,0);
    }

    float cu[2][4][4], cg[2][4][4];
#pragma unroll
    for (int i = 0; i < 2; i++)
#pragma unroll
        for (int j = 0; j < 4; j++)
#pragma unroll
            for (int r = 0; r < 4; r++){ cu[i][j][r] = 0.f; cg[i][j][r] = 0.f; }

#define G1_STAGE(s, cidx) {                                                     \
    if (aSrc) cp16(s2u(uA + (s)*1280 + amr*20 + (akb>>1)), aSrc + (cidx)*16);   \
    _Pragma("unroll")                                                           \
    for (int c2 = 0; c2 < 2; c2++){                                             \
        int kp_ = bkp + c2*8;                                                   \
        const uint32_t* wr_ = Wrow + (size_t)((cidx)*16 + kp_)*W1ROW + n0 + bn4;\
        cp16(s2u(uBu + (s)*2176 + kp_*136 + bn4), wr_);                         \
        cp16(s2u(uBg + (s)*2176 + kp_*136 + bn4), wr_ + W1HALF);                \
    } }

    const int NC = DD/32;   // 16
    G1_STAGE(0, 0); CP_COMMIT();
    G1_STAGE(1, 1); CP_COMMIT();
    for (int c = 0; c < NC; c++){
        CP_WAIT1();
        __syncthreads();
        int s = c % 3;
        uint32_t* pA  = uA  + s*1280;
        uint32_t* pBu = uBu + s*2176;
        uint32_t* pBg = uBg + s*2176;
#pragma unroll
        for (int ks = 0; ks < 2; ks++){
            int kpb = ks * 8;
            uint32_t a[2][4];
#pragma unroll
            for (int mi = 0; mi < 2; mi++){
                int row = wm*32 + mi*16 + (lane & 15);
                uint32_t addr = s2u(pA + row*20 + kpb + ((lane >> 4) << 2));
                LDMX4(a[mi][0], a[mi][1], a[mi][2], a[mi][3], addr);
            }
#pragma unroll
            for (int ni = 0; ni < 4; ni++){
                int nb = wn*32 + ni*8 + group;
                uint32_t bu0 = pBu[(kpb+tig)*136 + nb], bu1 = pBu[(kpb+tig+4)*136 + nb];
                uint32_t bg0 = pBg[(kpb+tig)*136 + nb], bg1 = pBg[(kpb+tig+4)*136 + nb];
#pragma unroll
                for (int mi = 0; mi < 2; mi++){
                    mma16(cu[mi][ni], a[mi][0],a[mi][1],a[mi][2],a[mi][3], bu0, bu1);
                    mma16(cg[mi][ni], a[mi][0],a[mi][1],a[mi][2],a[mi][3], bg0, bg1);
                }
            }
        }
        int nx = c + 2;
        if (nx < NC){ G1_STAGE(nx % 3, nx); }
        CP_COMMIT();
    }
#undef G1_STAGE

    // ---- GEGLU epilogue: packed bf16 pairs ----
    const float* b1e = b1 + (size_t)e * TWOH;
    const float* mbe = mb + (size_t)e * HH;
#pragma unroll
    for (int mi = 0; mi < 2; mi++){
#pragma unroll
        for (int rp = 0; rp < 2; rp++){
            int row = m0 + wm*32 + mi*16 + group + rp*8;
            size_t rowoff = ((size_t)be*CAP + row) * ACTS;
#pragma unroll
            for (int ni = 0; ni < 4; ni++){
                int col = n0 + wn*32 + ni*8 + tig*2;
                if (col < ACTS){
                    float lo = 0.f, hi = 0.f;
                    if (col < HH){
                        float u  = cu[mi][ni][rp*2]   + b1e[col];
                        float gv = cg[mi][ni][rp*2]   + b1e[col + HH];
                        lo = u * (0.5f * gv * (1.f + erff(gv * 0.7071067811865476f))) * mbe[col];
                    }
                    if (col + 1 < HH){
                        float u  = cu[mi][ni][rp*2+1] + b1e[col+1];
                        float gv = cg[mi][ni][rp*2+1] + b1e[col+1 + HH];
                        hi = u * (0.5f * gv * (1.f + erff(gv * 0.7071067811865476f))) * mbe[col+1];
                    }
                    g_acth[(rowoff + col) >> 1] = pack2(lo, hi);
                }
            }
        }
    }
}

// ================= K4: GEMM2 (bf16 mma, 3-stage cp.async, 1 bar/chunk) ==========
__global__ __launch_bounds__(256) void k_gemm2(const float* __restrict__ b2){
    __shared__ uint32_t sA[3][64][20];
    __shared__ uint32_t sB[3][16][136];

    int be = blockIdx.z, e = be & 7;
    int m0 = blockIdx.y * 64, n0 = blockIdx.x * 128;
    int tid = threadIdx.x;
    int lane = tid & 31, wid = tid >> 5;
    int group = lane >> 2, tig = lane & 3;
    int wm = wid >> 2, wn = wid & 3;

    int amr = tid & 63;
    int akb = (tid >> 6) * 8;
    const uint32_t* aSrc = &g_acth[(((size_t)be*CAP + m0 + amr)*ACTS + akb) >> 1];
    int bkp = tid >> 5;
    int bn4 = (tid & 31) * 4;
    const uint32_t* Wrow = g_w2h + (size_t)e*W2KP*512;

    float cc[2][4][4];
#pragma unroll
    for (int i = 0; i < 2; i++)
#pragma unroll
        for (int j = 0; j < 4; j++)
#pragma unroll
            for (int r = 0; r < 4; r++) cc[i][j][r] = 0.f;

#define G2_STAGE(s, cidx) {                                                     \
    cp16(s2u(&sA[s][amr][akb>>1]), aSrc + (cidx)*16);                           \
    _Pragma("unroll")                                                           \
    for (int c2 = 0; c2 < 2; c2++){                                             \
        int kp_ = bkp + c2*8;                                                   \
        cp16(s2u(&sB[s][kp_][bn4]), Wrow + (size_t)((cidx)*16 + kp_)*512 + n0 + bn4);\
    } }

    const int NC = ACTS/32;   // 43
    G2_STAGE(0, 0); CP_COMMIT();
    G2_STAGE(1, 1); CP_COMMIT();
    for (int c = 0; c < NC; c++){
        CP_WAIT1();
        __syncthreads();
        int s = c % 3;
#pragma unroll
        for (int ks = 0; ks < 2; ks++){
            int kpb = ks * 8;
            uint32_t a[2][4];
#pragma unroll
            for (int mi = 0; mi < 2; mi++){
                int row = wm*32 + mi*16 + (lane & 15);
                uint32_t addr = s2u(&sA[s][row][kpb + ((lane >> 4) << 2)]);
                LDMX4(a[mi][0], a[mi][1], a[mi][2], a[mi][3], addr);
            }
#pragma unroll
            for (int ni = 0; ni < 4; ni++){
                int nb = wn*32 + ni*8 + group;
                uint32_t b0 = sB[s][kpb+tig][nb], b1v = sB[s][kpb+tig+4][nb];
#pragma unroll
                for (int mi = 0; mi < 2; mi++)
                    mma16(cc[mi][ni], a[mi][0],a[mi][1],a[mi][2],a[mi][3], b0, b1v);
            }
        }
        int nx = c + 2;
        if (nx < NC){ G2_STAGE(nx % 3, nx); }
        CP_COMMIT();
    }
#undef G2_STAGE

    const float* b2e = b2 + (size_t)e * DD;
#pragma unroll
    for (int mi = 0; mi < 2; mi++){
#pragma unroll
        for (int rp = 0; rp < 2; rp++){
            int row = m0 + wm*32 + mi*16 + group + rp*8;
            float* orow = &g_eo[((size_t)be*CAP + row) * DD];
#pragma unroll
            for (int ni = 0; ni < 4; ni++){
                int col = n0 + wn*32 + ni*8 + tig*2;
                orow[col]   = cc[mi][ni][rp*2]   + b2e[col];
                orow[col+1] = cc[mi][ni][rp*2+1] + b2e[col+1];
            }
        }
    }
}

// ================= K5: combine + residual + LayerNorm =================
__global__ __launch_bounds__(256) void k_combine(const float* __restrict__ x,
                                                 const float* __restrict__ lng,
                                                 const float* __restrict__ lnb,
                                                 float* __restrict__ out){
    int t = blockIdx.x * 8 + (threadIdx.x >> 5);
    int lane = threadIdx.x & 31;
    int b = t / NN;
    int c1 = g_c1[t], c2 = g_c2[t];
    float w1g = (c1 >= 0) ? g_g1[t] : 0.f;
    float w2g = (c2 >= 0) ? g_g2[t] : 0.f;
    const float* eo1 = &g_eo[(((size_t)(b*EE + g_e1[t]))*CAP + (c1 >= 0 ? c1 : 0)) * DD];
    const float* eo2 = &g_eo[(((size_t)(b*EE + g_e2[t]))*CAP + (c2 >= 0 ? c2 : 0)) * DD];
    const float* xr = x + (size_t)t * DD;

    float y[16];
    float s = 0.f, s2 = 0.f;
#pragma unroll
    for (int j = 0; j < 4; j++){
        int d4 = (j*32 + lane) * 4;
        float4 xv = *reinterpret_cast<const float4*>(xr + d4);
        float4 a  = *reinterpret_cast<const float4*>(eo1 + d4);
        float4 c  = *reinterpret_cast<const float4*>(eo2 + d4);
        float yv[4] = { xv.x + w1g*a.x + w2g*c.x,
                        xv.y + w1g*a.y + w2g*c.y,
                        xv.z + w1g*a.z + w2g*c.z,
                        xv.w + w1g*a.w + w2g*c.w };
#pragma unroll
        for (int q = 0; q < 4; q++){
            y[j*4+q] = yv[q];
            s += yv[q]; s2 += yv[q]*yv[q];
        }
    }
#pragma unroll
    for (int off = 16; off; off >>= 1){
        s  += __shfl_xor_sync(0xffffffffu, s,  off);
        s2 += __shfl_xor_sync(0xffffffffu, s2, off);
    }
    float mu = s * (1.f/512.f);
    float var = s2 * (1.f/512.f) - mu*mu;
    float iv = rsqrtf(var + 1e-5f);
#pragma unroll
    for (int j = 0; j < 4; j++){
        int d4 = (j*32 + lane) * 4;
        float4 gv = *reinterpret_cast<const float4*>(lng + d4);
        float4 bv = *reinterpret_cast<const float4*>(lnb + d4);
        float4 ov;
        ov.x = (y[j*4+0]-mu)*iv*gv.x + bv.x;
        ov.y = (y[j*4+1]-mu)*iv*gv.y + bv.y;
        ov.z = (y[j*4+2]-mu)*iv*gv.z + bv.z;
        ov.w = (y[j*4+3]-mu)*iv*gv.w + bv.w;
        *reinterpret_cast<float4*>(out + (size_t)t*DD + d4) = ov;
    }
}

// ================= launch =================
extern "C" void kernel_launch(void* const* d_in, const int* in_sizes, int n_in,
                              void* d_out, int out_size){
    const float* x    = (const float*)d_in[0];
    const float* gw   = (const float*)d_in[1];
    const float* png  = (const float*)d_in[2];
    const float* w1   = (const float*)d_in[3];
    const float* b1   = (const float*)d_in[4];
    const float* mb   = (const float*)d_in[5];
    const float* w2   = (const float*)d_in[6];
    const float* b2   = (const float*)d_in[7];
    const float* lng  = (const float*)d_in[8];
    const float* lnb  = (const float*)d_in[9];
    float* out = (float*)d_out;

    const int G1_SMEM = (3*1280 + 3*2176 + 3*2176) * 4;   // 67584 B
    static bool attr_set = false;
    if (!attr_set){
        cudaFuncSetAttribute(k_gemm1, cudaFuncAttributeMaxDynamicSharedMemorySize, G1_SMEM);
        attr_set = true;
    }

    k_init<<<1, 64>>>();
    {
        int items1 = EE*256*2*(W1HALF/4);
        k_conv1<<<(items1 + 255)/256, 256>>>(w1);
        int items2 = EE*W2KP*128;
        k_conv2<<<(items2 + 255)/256, 256>>>(w2);
    }
    k_gate<<<BN/8, 256>>>(x, gw, png);
    k_scan<<<1, 1024>>>(out, out_size);
    k_gemm1<<<dim3((HH+127)/128, CAP/64, BE), 256, G1_SMEM>>>(b1, mb);
    k_gemm2<<<dim3(DD/128, CAP/64, BE), 256>>>(b2);
    k_combine<<<BN/8, 256>>>(x, lng, lnb, out);
}